// round 12
// baseline (speedup 1.0000x reference)
#include <cuda_runtime.h>
#include <math.h>
#include <stdint.h>

#define NN 100000
#define EE 1600000
#define ET (EE + NN)
#define SLOPE 0.2f
#define NCH 4

// chunk boundaries in nodes (multiples of 64 except the last)
static inline int chunk_lo(int c) {
    const int b[NCH + 1] = {0, 25024, 50048, 75072, 100000};
    return b[c];
}

// ---------------- scratch (static device globals; no runtime allocation) ----------------
// double-buffered per-layer products (ping-pong A/B so chunked GEMM(l+1) never
// overwrites data still being read by agg(l))
__device__ __align__(16) float g_hA[NN * 128];
__device__ __align__(16) float g_hB[NN * 128];
__device__ __align__(16) float g_feat[NN * 128];  // layer activations (post bias+ELU)
__device__ __align__(16) float g_asA[NN * 4];
__device__ __align__(16) float g_adA[NN * 4];
__device__ __align__(16) float g_asB[NN * 4];
__device__ __align__(16) float g_adB[NN * 4];
__device__ int g_off[NN + 1];                     // CSR offsets (by dst)
__device__ int g_cur[NN];                         // scatter cursors
__device__ int g_csr[ET];                         // CSR: src index per incoming edge

// ---------------- CSR build ----------------
__global__ void k_init() {
    int i = blockIdx.x * blockDim.x + threadIdx.x;
    if (i < NN) g_off[i] = 1;  // self loop
}

__global__ void k_count(const int* __restrict__ dst) {
    int i = blockIdx.x * blockDim.x + threadIdx.x;
    if (i < EE) atomicAdd(&g_off[dst[i]], 1);
}

// single-block exclusive scan over g_off[0..NN-1], in place; writes g_cur too.
__global__ void k_scan() {
    __shared__ int swarp[32];
    __shared__ int s_carry;
    int t = threadIdx.x, lane = t & 31, wid = t >> 5;
    if (t == 0) s_carry = 0;
    __syncthreads();
    for (int base = 0; base < NN; base += 1024) {
        int i = base + t;
        int v = (i < NN) ? g_off[i] : 0;
        int c = s_carry;
        int x = v;
#pragma unroll
        for (int o = 1; o < 32; o <<= 1) {
            int y = __shfl_up_sync(0xffffffffu, x, o);
            if (lane >= o) x += y;
        }
        if (lane == 31) swarp[wid] = x;
        __syncthreads();
        if (wid == 0) {
            int y = swarp[lane];
#pragma unroll
            for (int o = 1; o < 32; o <<= 1) {
                int z = __shfl_up_sync(0xffffffffu, y, o);
                if (lane >= o) y += z;
            }
            swarp[lane] = y;
        }
        __syncthreads();
        int incl = x + ((wid > 0) ? swarp[wid - 1] : 0) + c;
        int excl = incl - v;
        if (i < NN) { g_off[i] = excl; g_cur[i] = excl; }
        __syncthreads();
        if (t == 0) s_carry = c + swarp[31];
        __syncthreads();
    }
    if (threadIdx.x == 0) g_off[NN] = s_carry;  // = ET
}

__global__ void k_scatter(const int* __restrict__ src, const int* __restrict__ dst) {
    int i = blockIdx.x * blockDim.x + threadIdx.x;
    if (i < ET) {
        int s, d;
        if (i < EE) { s = src[i]; d = dst[i]; }
        else        { s = i - EE; d = s; }
        int pos = atomicAdd(&g_cur[d], 1);
        g_csr[pos] = s;
    }
}

// ---------------- tf32 helpers ----------------
__device__ __forceinline__ uint32_t f2tf(float f) {
    uint32_t u;
    asm("cvt.rna.tf32.f32 %0, %1;" : "=r"(u) : "f"(f));
    return u;
}

__device__ __forceinline__ void mma_tf32(float4& c, const uint32_t* a, uint32_t b0, uint32_t b1) {
    asm volatile(
        "mma.sync.aligned.m16n8k8.row.col.f32.tf32.tf32.f32 "
        "{%0,%1,%2,%3}, {%4,%5,%6,%7}, {%8,%9}, {%0,%1,%2,%3};\n"
        : "+f"(c.x), "+f"(c.y), "+f"(c.z), "+f"(c.w)
        : "r"(a[0]), "r"(a[1]), "r"(a[2]), "r"(a[3]), "r"(b0), "r"(b1));
}

// ---------------- tensor-core GEMM (3xTF32) + fused attention scalars ----------------
// handles rows [rbase0, rbase0 + gridDim.x*64) of X
template <int H>
__global__ void __launch_bounds__(128, 2) k_gemm(
        const float* __restrict__ X, const float* __restrict__ W,
        const float* __restrict__ asrc, const float* __restrict__ adst,
        float* __restrict__ Hout, float* __restrict__ As, float* __restrict__ Ad,
        int rbase0) {
    extern __shared__ float sm[];
    float* Ws = sm;              // 16384 floats
    float* Xs = sm + 16384;      // 8192 floats
    float* s_red = sm + 24576;   // 256 floats (H==1 cross-warp reduce)
    int t = threadIdx.x;
    int lane = t & 31, wid = t >> 5;
    int wm = wid >> 1, wn = wid & 1;
    int q = lane >> 2;           // 0..7
    int rr = lane & 3;           // 0..3
    int rbase = rbase0 + blockIdx.x * 64;

    // ---- load W (swizzled) ----
    const float4* W4 = (const float4*)W;
    float4* Ws4 = (float4*)Ws;
#pragma unroll
    for (int i = 0; i < 32; i++) {
        int idx = t + i * 128;              // 0..4095
        int k = idx >> 5, c4 = idx & 31;
        Ws4[k * 32 + (c4 ^ ((k & 3) << 1))] = W4[idx];
    }
    // ---- load X tile (swizzled, zero-padded) ----
    const float4* X4 = (const float4*)X;
    float4* Xs4 = (float4*)Xs;
#pragma unroll
    for (int i = 0; i < 16; i++) {
        int idx = t + i * 128;
        int row = idx >> 5, c4 = idx & 31;
        int r = rbase + row;
        float4 v = make_float4(0.f, 0.f, 0.f, 0.f);
        if (r < NN) v = X4[r * 32 + c4];
        Xs4[row * 32 + (c4 ^ (row & 7))] = v;
    }
    __syncthreads();

    float4 C[2][8];
#pragma unroll
    for (int mt = 0; mt < 2; mt++)
#pragma unroll
        for (int n = 0; n < 8; n++) C[mt][n] = make_float4(0.f, 0.f, 0.f, 0.f);

    int asw = q << 2;  // A swizzle
    int bsw = rr << 3; // B swizzle

#pragma unroll 2
    for (int kc = 0; kc < 16; kc++) {
        int k0 = kc * 8 + rr;
        uint32_t Ah[2][4], Al[2][4];
#pragma unroll
        for (int mt = 0; mt < 2; mt++) {
            int r0 = wm * 32 + mt * 16 + q;
            int r1 = r0 + 8;
            float a0 = Xs[r0 * 128 + (k0 ^ asw)];
            float a1 = Xs[r1 * 128 + (k0 ^ asw)];
            float a2 = Xs[r0 * 128 + ((k0 + 4) ^ asw)];
            float a3 = Xs[r1 * 128 + ((k0 + 4) ^ asw)];
            Ah[mt][0] = f2tf(a0); Al[mt][0] = f2tf(a0 - __uint_as_float(Ah[mt][0]));
            Ah[mt][1] = f2tf(a1); Al[mt][1] = f2tf(a1 - __uint_as_float(Ah[mt][1]));
            Ah[mt][2] = f2tf(a2); Al[mt][2] = f2tf(a2 - __uint_as_float(Ah[mt][2]));
            Ah[mt][3] = f2tf(a3); Al[mt][3] = f2tf(a3 - __uint_as_float(Ah[mt][3]));
        }
#pragma unroll
        for (int n = 0; n < 8; n++) {
            int col = wn * 64 + n * 8 + q;
            float b0f = Ws[k0 * 128 + (col ^ bsw)];
            float b1f = Ws[(k0 + 4) * 128 + (col ^ bsw)];
            uint32_t b0h = f2tf(b0f), b1h = f2tf(b1f);
            uint32_t b0l = f2tf(b0f - __uint_as_float(b0h));
            uint32_t b1l = f2tf(b1f - __uint_as_float(b1h));
#pragma unroll
            for (int mt = 0; mt < 2; mt++) {
                mma_tf32(C[mt][n], Al[mt], b0h, b1h);
                mma_tf32(C[mt][n], Ah[mt], b0l, b1l);
                mma_tf32(C[mt][n], Ah[mt], b0h, b1h);
            }
        }
    }

    // ---- epilogue: store H + fused attention scalars ----
#pragma unroll
    for (int mt = 0; mt < 2; mt++) {
        int rt0 = wm * 32 + mt * 16 + q;  // tile row (0..63)
        int gr0 = rbase + rt0;
        int gr1 = gr0 + 8;

#pragma unroll
        for (int n = 0; n < 8; n++) {
            int col = wn * 64 + n * 8 + 2 * rr;
            if (gr0 < NN) *(float2*)&Hout[gr0 * 128 + col] = make_float2(C[mt][n].x, C[mt][n].y);
            if (gr1 < NN) *(float2*)&Hout[gr1 * 128 + col] = make_float2(C[mt][n].z, C[mt][n].w);
        }

        if (H == 4) {
#pragma unroll
            for (int hh = 0; hh < 2; hh++) {
                float ps0 = 0.f, pd0 = 0.f, ps1 = 0.f, pd1 = 0.f;
#pragma unroll
                for (int j = 0; j < 4; j++) {
                    int n = hh * 4 + j;
                    int col = wn * 64 + n * 8 + 2 * rr;
                    float2 sv = *(const float2*)&asrc[col];
                    float2 dv = *(const float2*)&adst[col];
                    ps0 += C[mt][n].x * sv.x + C[mt][n].y * sv.y;
                    ps1 += C[mt][n].z * sv.x + C[mt][n].w * sv.y;
                    pd0 += C[mt][n].x * dv.x + C[mt][n].y * dv.y;
                    pd1 += C[mt][n].z * dv.x + C[mt][n].w * dv.y;
                }
#pragma unroll
                for (int o = 1; o <= 2; o <<= 1) {
                    ps0 += __shfl_xor_sync(0xffffffffu, ps0, o);
                    ps1 += __shfl_xor_sync(0xffffffffu, ps1, o);
                    pd0 += __shfl_xor_sync(0xffffffffu, pd0, o);
                    pd1 += __shfl_xor_sync(0xffffffffu, pd1, o);
                }
                if (rr == 0) {
                    int head = wn * 2 + hh;
                    if (gr0 < NN) { As[gr0 * 4 + head] = ps0; Ad[gr0 * 4 + head] = pd0; }
                    if (gr1 < NN) { As[gr1 * 4 + head] = ps1; Ad[gr1 * 4 + head] = pd1; }
                }
            }
        } else {
            float ps0 = 0.f, pd0 = 0.f, ps1 = 0.f, pd1 = 0.f;
#pragma unroll
            for (int n = 0; n < 8; n++) {
                int col = wn * 64 + n * 8 + 2 * rr;
                float2 sv = *(const float2*)&asrc[col];
                float2 dv = *(const float2*)&adst[col];
                ps0 += C[mt][n].x * sv.x + C[mt][n].y * sv.y;
                ps1 += C[mt][n].z * sv.x + C[mt][n].w * sv.y;
                pd0 += C[mt][n].x * dv.x + C[mt][n].y * dv.y;
                pd1 += C[mt][n].z * dv.x + C[mt][n].w * dv.y;
            }
#pragma unroll
            for (int o = 1; o <= 2; o <<= 1) {
                ps0 += __shfl_xor_sync(0xffffffffu, ps0, o);
                ps1 += __shfl_xor_sync(0xffffffffu, ps1, o);
                pd0 += __shfl_xor_sync(0xffffffffu, pd0, o);
                pd1 += __shfl_xor_sync(0xffffffffu, pd1, o);
            }
            if (rr == 0) {
                s_red[wn * 128 + rt0] = ps0;
                s_red[wn * 128 + 64 + rt0] = pd0;
                s_red[wn * 128 + rt0 + 8] = ps1;
                s_red[wn * 128 + 64 + rt0 + 8] = pd1;
            }
        }
    }

    if (H == 1) {
        __syncthreads();
        if (t < 64) {
            int r = rbase + t;
            if (r < NN) {
                As[r] = s_red[t] + s_red[128 + t];
                Ad[r] = s_red[64 + t] + s_red[192 + t];
            }
        }
    }
}

// ---------------- warp-per-node aggregation (node range [node_base, node_end)) ----------------
#define AGG_CACHE 64
template <int H, bool ELU>
__global__ void __launch_bounds__(256) k_agg(
        const float* __restrict__ Hf, const float* __restrict__ As,
        const float* __restrict__ Ad, const float* __restrict__ bias,
        float* __restrict__ out, int node_base, int node_end) {
    __shared__ int   s_idx[8][AGG_CACHE];
    __shared__ float s_lg[8][AGG_CACHE * 4];
    int wip = threadIdx.x >> 5;  // warp in block
    int warp = node_base + ((blockIdx.x * blockDim.x + threadIdx.x) >> 5);
    int lane = threadIdx.x & 31;
    if (warp >= node_end) return;
    int e0 = g_off[warp], e1 = g_off[warp + 1];
    int deg = e1 - e0;
    int head = (H == 4) ? (lane >> 3) : 0;

    float4 adv4;
    if (H == 4) adv4 = ((const float4*)Ad)[warp];
    else        adv4 = make_float4(Ad[warp], 0.f, 0.f, 0.f);

    // ---- pass 1: lane-parallel logits + per-head max ----
    float m0 = -1e30f, m1 = -1e30f, m2 = -1e30f, m3 = -1e30f;
    for (int j = lane; j < deg; j += 32) {
        int s = g_csr[e0 + j];
        if (H == 4) {
            float4 a4 = ((const float4*)As)[s];
            float l0 = a4.x + adv4.x; l0 = (l0 > 0.f) ? l0 : SLOPE * l0;
            float l1 = a4.y + adv4.y; l1 = (l1 > 0.f) ? l1 : SLOPE * l1;
            float l2 = a4.z + adv4.z; l2 = (l2 > 0.f) ? l2 : SLOPE * l2;
            float l3 = a4.w + adv4.w; l3 = (l3 > 0.f) ? l3 : SLOPE * l3;
            if (j < AGG_CACHE) {
                s_idx[wip][j] = s;
                *(float4*)&s_lg[wip][j * 4] = make_float4(l0, l1, l2, l3);
            }
            m0 = fmaxf(m0, l0); m1 = fmaxf(m1, l1);
            m2 = fmaxf(m2, l2); m3 = fmaxf(m3, l3);
        } else {
            float l = As[s] + adv4.x;
            l = (l > 0.f) ? l : SLOPE * l;
            if (j < AGG_CACHE) { s_idx[wip][j] = s; s_lg[wip][j * 4] = l; }
            m0 = fmaxf(m0, l);
        }
    }
#pragma unroll
    for (int o = 16; o >= 1; o >>= 1) {
        m0 = fmaxf(m0, __shfl_xor_sync(0xffffffffu, m0, o));
        if (H == 4) {
            m1 = fmaxf(m1, __shfl_xor_sync(0xffffffffu, m1, o));
            m2 = fmaxf(m2, __shfl_xor_sync(0xffffffffu, m2, o));
            m3 = fmaxf(m3, __shfl_xor_sync(0xffffffffu, m3, o));
        }
    }
    float m = m0;
    if (H == 4) m = (head == 0) ? m0 : (head == 1) ? m1 : (head == 2) ? m2 : m3;
    float adv = (H == 4) ? ((head == 0) ? adv4.x : (head == 1) ? adv4.y
                           : (head == 2) ? adv4.z : adv4.w)
                         : adv4.x;
    __syncwarp();

    // ---- pass 2: gather + exp + accumulate ----
    const float4* H4 = (const float4*)Hf;
    float den = 0.f;
    float4 acc = make_float4(0.f, 0.f, 0.f, 0.f);
    int cached = (deg < AGG_CACHE) ? deg : AGG_CACHE;
    int e = 0;
    for (; e + 8 <= cached; e += 8) {
        int s[8];
        float w[8];
        float4 hv[8];
#pragma unroll
        for (int j = 0; j < 8; j++) s[j] = s_idx[wip][e + j];
#pragma unroll
        for (int j = 0; j < 8; j++) hv[j] = H4[s[j] * 32 + lane];
#pragma unroll
        for (int j = 0; j < 8; j++) w[j] = __expf(s_lg[wip][(e + j) * 4 + head] - m);
#pragma unroll
        for (int j = 0; j < 8; j++) {
            den += w[j];
            acc.x = fmaf(w[j], hv[j].x, acc.x);
            acc.y = fmaf(w[j], hv[j].y, acc.y);
            acc.z = fmaf(w[j], hv[j].z, acc.z);
            acc.w = fmaf(w[j], hv[j].w, acc.w);
        }
    }
    for (; e < cached; e++) {
        int s = s_idx[wip][e];
        float w = __expf(s_lg[wip][e * 4 + head] - m);
        float4 hv = H4[s * 32 + lane];
        den += w;
        acc.x = fmaf(w, hv.x, acc.x);
        acc.y = fmaf(w, hv.y, acc.y);
        acc.z = fmaf(w, hv.z, acc.z);
        acc.w = fmaf(w, hv.w, acc.w);
    }
    // overflow path (deg > AGG_CACHE; rare)
    for (int eo = cached; eo < deg; eo++) {
        int s = g_csr[e0 + eo];
        float a = As[s * H + head] + adv;
        a = (a > 0.f) ? a : SLOPE * a;
        float w = __expf(a - m);
        float4 hv = H4[s * 32 + lane];
        den += w;
        acc.x = fmaf(w, hv.x, acc.x);
        acc.y = fmaf(w, hv.y, acc.y);
        acc.z = fmaf(w, hv.z, acc.z);
        acc.w = fmaf(w, hv.w, acc.w);
    }

    float inv = 1.f / den;
    float4 b = ((const float4*)bias)[lane];
    float4 o;
    o.x = acc.x * inv + b.x;
    o.y = acc.y * inv + b.y;
    o.z = acc.z * inv + b.z;
    o.w = acc.w * inv + b.w;
    if (ELU) {
        o.x = (o.x > 0.f) ? o.x : expm1f(o.x);
        o.y = (o.y > 0.f) ? o.y : expm1f(o.y);
        o.z = (o.z > 0.f) ? o.z : expm1f(o.z);
        o.w = (o.w > 0.f) ? o.w : expm1f(o.w);
    }
    ((float4*)out)[warp * 32 + lane] = o;
}

// ---------------- host launcher ----------------
extern "C" void kernel_launch(void* const* d_in, const int* in_sizes, int n_in,
                              void* d_out, int out_size) {
    const float* x   = (const float*)d_in[0];
    const int*   ei  = (const int*)d_in[1];
    const float* W1  = (const float*)d_in[2];
    const float* as1 = (const float*)d_in[3];
    const float* ad1 = (const float*)d_in[4];
    const float* b1  = (const float*)d_in[5];
    const float* W2  = (const float*)d_in[6];
    const float* as2 = (const float*)d_in[7];
    const float* ad2 = (const float*)d_in[8];
    const float* b2  = (const float*)d_in[9];
    const float* W3  = (const float*)d_in[10];
    const float* as3 = (const float*)d_in[11];
    const float* ad3 = (const float*)d_in[12];
    const float* b3  = (const float*)d_in[13];
    const int* src = ei;
    const int* dst = ei + EE;

    const int smem_gemm = (16384 + 8192 + 256) * 4;  // ~97 KB
    cudaFuncSetAttribute(k_gemm<4>, cudaFuncAttributeMaxDynamicSharedMemorySize, smem_gemm);
    cudaFuncSetAttribute(k_gemm<1>, cudaFuncAttributeMaxDynamicSharedMemorySize, smem_gemm);

    float *d_hA, *d_hB, *d_feat, *d_AsA, *d_AdA, *d_AsB, *d_AdB;
    cudaGetSymbolAddress((void**)&d_hA, g_hA);
    cudaGetSymbolAddress((void**)&d_hB, g_hB);
    cudaGetSymbolAddress((void**)&d_feat, g_feat);
    cudaGetSymbolAddress((void**)&d_AsA, g_asA);
    cudaGetSymbolAddress((void**)&d_AdA, g_adA);
    cudaGetSymbolAddress((void**)&d_AsB, g_asB);
    cudaGetSymbolAddress((void**)&d_AdB, g_adB);

    // side stream + events (host objects, created once; no device memory)
    static cudaStream_t s2 = nullptr;
    static cudaEvent_t ev_fork = nullptr, ev_csr = nullptr, ev_g2 = nullptr, ev_g3 = nullptr;
    static cudaEvent_t ev_a1[NCH], ev_a2[NCH];
    if (!s2) {
        cudaStreamCreateWithFlags(&s2, cudaStreamNonBlocking);
        cudaEventCreateWithFlags(&ev_fork, cudaEventDisableTiming);
        cudaEventCreateWithFlags(&ev_csr, cudaEventDisableTiming);
        cudaEventCreateWithFlags(&ev_g2, cudaEventDisableTiming);
        cudaEventCreateWithFlags(&ev_g3, cudaEventDisableTiming);
        for (int c = 0; c < NCH; c++) {
            cudaEventCreateWithFlags(&ev_a1[c], cudaEventDisableTiming);
            cudaEventCreateWithFlags(&ev_a2[c], cudaEventDisableTiming);
        }
    }

    const int gemm_blocks_all = (NN + 63) / 64;  // 1563
    const int edge_blocks = (EE + 255) / 256;

    // ---- fork: CSR build on side stream, overlapped with layer-1 GEMM ----
    cudaEventRecord(ev_fork, 0);
    cudaStreamWaitEvent(s2, ev_fork, 0);
    k_init<<<(NN + 255) / 256, 256, 0, s2>>>();
    k_count<<<edge_blocks, 256, 0, s2>>>(dst);
    k_scan<<<1, 1024, 0, s2>>>();
    k_scatter<<<(ET + 255) / 256, 256, 0, s2>>>(src, dst);
    cudaEventRecord(ev_csr, s2);

    // ---- layer 1 GEMM -> buffer A (default stream, concurrent with CSR build) ----
    k_gemm<4><<<gemm_blocks_all, 128, smem_gemm>>>(x, W1, as1, ad1, d_hA, d_AsA, d_AdA, 0);
    cudaStreamWaitEvent(0, ev_csr, 0);  // CSR ready before agg

    // ---- boundary 1: agg1 (reads A) pipelined with gemm2 (writes B) ----
    for (int c = 0; c < NCH; c++) {
        int lo = chunk_lo(c), hi = chunk_lo(c + 1);
        int nodes = hi - lo;
        k_agg<4, true><<<(nodes + 7) / 8, 256>>>(d_hA, d_AsA, d_AdA, b1, d_feat, lo, hi);
        cudaEventRecord(ev_a1[c], 0);
        cudaStreamWaitEvent(s2, ev_a1[c], 0);
        int gblocks = (nodes + 63) / 64;
        k_gemm<4><<<gblocks, 128, smem_gemm, s2>>>(d_feat, W2, as2, ad2, d_hB, d_AsB, d_AdB, lo);
    }
    cudaEventRecord(ev_g2, s2);
    cudaStreamWaitEvent(0, ev_g2, 0);

    // ---- boundary 2: agg2 (reads B) pipelined with gemm3 (writes A) ----
    for (int c = 0; c < NCH; c++) {
        int lo = chunk_lo(c), hi = chunk_lo(c + 1);
        int nodes = hi - lo;
        k_agg<4, true><<<(nodes + 7) / 8, 256>>>(d_hB, d_AsB, d_AdB, b2, d_feat, lo, hi);
        cudaEventRecord(ev_a2[c], 0);
        cudaStreamWaitEvent(s2, ev_a2[c], 0);
        int gblocks = (nodes + 63) / 64;
        k_gemm<1><<<gblocks, 128, smem_gemm, s2>>>(d_feat, W3, as3, ad3, d_hA, d_AsA, d_AdA, lo);
    }
    cudaEventRecord(ev_g3, s2);
    cudaStreamWaitEvent(0, ev_g3, 0);

    // ---- final aggregation (reads A; heads=1, no ELU) ----
    k_agg<1, false><<<(NN + 7) / 8, 256>>>(d_hA, d_AsA, d_AdA, b3, (float*)d_out, 0, NN);
}

// round 13
// speedup vs baseline: 1.1939x; 1.1939x over previous
#include <cuda_runtime.h>
#include <cuda_fp16.h>
#include <math.h>
#include <stdint.h>

#define NN 100000
#define EE 1600000
#define ET (EE + NN)
#define SLOPE 0.2f

// ---------------- scratch (static device globals; no runtime allocation) ----------------
__device__ __align__(16) __half g_h[NN * 128];    // transformed features (fp16 for gather)
__device__ __align__(16) float g_feat[NN * 128];  // layer activations (post bias+ELU)
__device__ __align__(16) float g_as[NN * 4];      // per-node attention src scalar (per head)
__device__ __align__(16) float g_ad[NN * 4];      // per-node attention dst scalar (per head)
__device__ int g_off[NN + 1];                     // CSR offsets (by dst)
__device__ int g_cur[NN];                         // scatter cursors
__device__ int g_csr[ET];                         // CSR: src index per incoming edge

// ---------------- CSR build ----------------
__global__ void k_init() {
    int i = blockIdx.x * blockDim.x + threadIdx.x;
    if (i < NN) g_off[i] = 1;  // self loop
}

__global__ void k_count(const int* __restrict__ dst) {
    int i = blockIdx.x * blockDim.x + threadIdx.x;
    if (i < EE) atomicAdd(&g_off[dst[i]], 1);
}

// single-block exclusive scan over g_off[0..NN-1], in place; writes g_cur too.
__global__ void k_scan() {
    __shared__ int swarp[32];
    __shared__ int s_carry;
    int t = threadIdx.x, lane = t & 31, wid = t >> 5;
    if (t == 0) s_carry = 0;
    __syncthreads();
    for (int base = 0; base < NN; base += 1024) {
        int i = base + t;
        int v = (i < NN) ? g_off[i] : 0;
        int c = s_carry;
        int x = v;
#pragma unroll
        for (int o = 1; o < 32; o <<= 1) {
            int y = __shfl_up_sync(0xffffffffu, x, o);
            if (lane >= o) x += y;
        }
        if (lane == 31) swarp[wid] = x;
        __syncthreads();
        if (wid == 0) {
            int y = swarp[lane];
#pragma unroll
            for (int o = 1; o < 32; o <<= 1) {
                int z = __shfl_up_sync(0xffffffffu, y, o);
                if (lane >= o) y += z;
            }
            swarp[lane] = y;
        }
        __syncthreads();
        int incl = x + ((wid > 0) ? swarp[wid - 1] : 0) + c;
        int excl = incl - v;
        if (i < NN) { g_off[i] = excl; g_cur[i] = excl; }
        __syncthreads();
        if (t == 0) s_carry = c + swarp[31];
        __syncthreads();
    }
    if (threadIdx.x == 0) g_off[NN] = s_carry;  // = ET
}

__global__ void k_scatter(const int* __restrict__ src, const int* __restrict__ dst) {
    int i = blockIdx.x * blockDim.x + threadIdx.x;
    if (i < ET) {
        int s, d;
        if (i < EE) { s = src[i]; d = dst[i]; }
        else        { s = i - EE; d = s; }
        int pos = atomicAdd(&g_cur[d], 1);
        g_csr[pos] = s;
    }
}

// ---------------- tf32 helpers ----------------
__device__ __forceinline__ uint32_t f2tf(float f) {
    uint32_t u;
    asm("cvt.rna.tf32.f32 %0, %1;" : "=r"(u) : "f"(f));
    return u;
}

__device__ __forceinline__ void mma_tf32(float4& c, const uint32_t* a, uint32_t b0, uint32_t b1) {
    asm volatile(
        "mma.sync.aligned.m16n8k8.row.col.f32.tf32.tf32.f32 "
        "{%0,%1,%2,%3}, {%4,%5,%6,%7}, {%8,%9}, {%0,%1,%2,%3};\n"
        : "+f"(c.x), "+f"(c.y), "+f"(c.z), "+f"(c.w)
        : "r"(a[0]), "r"(a[1]), "r"(a[2]), "r"(a[3]), "r"(b0), "r"(b1));
}

// ---------------- tensor-core GEMM (3xTF32) + fused attention scalars ----------------
// Stores H in fp16 (halves the downstream gather traffic). As/Ad from fp32 accums.
template <int H>
__global__ void __launch_bounds__(128, 2) k_gemm(
        const float* __restrict__ X, const float* __restrict__ W,
        const float* __restrict__ asrc, const float* __restrict__ adst,
        __half* __restrict__ Hout, float* __restrict__ As, float* __restrict__ Ad) {
    extern __shared__ float sm[];
    float* Ws = sm;              // 16384 floats
    float* Xs = sm + 16384;      // 8192 floats
    float* s_red = sm + 24576;   // 256 floats (H==1 cross-warp reduce)
    int t = threadIdx.x;
    int lane = t & 31, wid = t >> 5;
    int wm = wid >> 1, wn = wid & 1;
    int q = lane >> 2;           // 0..7
    int rr = lane & 3;           // 0..3
    int rbase = blockIdx.x * 64;

    // ---- load W (swizzled) ----
    const float4* W4 = (const float4*)W;
    float4* Ws4 = (float4*)Ws;
#pragma unroll
    for (int i = 0; i < 32; i++) {
        int idx = t + i * 128;              // 0..4095
        int k = idx >> 5, c4 = idx & 31;
        Ws4[k * 32 + (c4 ^ ((k & 3) << 1))] = W4[idx];
    }
    // ---- load X tile (swizzled, zero-padded) ----
    const float4* X4 = (const float4*)X;
    float4* Xs4 = (float4*)Xs;
#pragma unroll
    for (int i = 0; i < 16; i++) {
        int idx = t + i * 128;
        int row = idx >> 5, c4 = idx & 31;
        int r = rbase + row;
        float4 v = make_float4(0.f, 0.f, 0.f, 0.f);
        if (r < NN) v = X4[r * 32 + c4];
        Xs4[row * 32 + (c4 ^ (row & 7))] = v;
    }
    __syncthreads();

    float4 C[2][8];
#pragma unroll
    for (int mt = 0; mt < 2; mt++)
#pragma unroll
        for (int n = 0; n < 8; n++) C[mt][n] = make_float4(0.f, 0.f, 0.f, 0.f);

    int asw = q << 2;  // A swizzle
    int bsw = rr << 3; // B swizzle

#pragma unroll 2
    for (int kc = 0; kc < 16; kc++) {
        int k0 = kc * 8 + rr;
        uint32_t Ah[2][4], Al[2][4];
#pragma unroll
        for (int mt = 0; mt < 2; mt++) {
            int r0 = wm * 32 + mt * 16 + q;
            int r1 = r0 + 8;
            float a0 = Xs[r0 * 128 + (k0 ^ asw)];
            float a1 = Xs[r1 * 128 + (k0 ^ asw)];
            float a2 = Xs[r0 * 128 + ((k0 + 4) ^ asw)];
            float a3 = Xs[r1 * 128 + ((k0 + 4) ^ asw)];
            Ah[mt][0] = f2tf(a0); Al[mt][0] = f2tf(a0 - __uint_as_float(Ah[mt][0]));
            Ah[mt][1] = f2tf(a1); Al[mt][1] = f2tf(a1 - __uint_as_float(Ah[mt][1]));
            Ah[mt][2] = f2tf(a2); Al[mt][2] = f2tf(a2 - __uint_as_float(Ah[mt][2]));
            Ah[mt][3] = f2tf(a3); Al[mt][3] = f2tf(a3 - __uint_as_float(Ah[mt][3]));
        }
#pragma unroll
        for (int n = 0; n < 8; n++) {
            int col = wn * 64 + n * 8 + q;
            float b0f = Ws[k0 * 128 + (col ^ bsw)];
            float b1f = Ws[(k0 + 4) * 128 + (col ^ bsw)];
            uint32_t b0h = f2tf(b0f), b1h = f2tf(b1f);
            uint32_t b0l = f2tf(b0f - __uint_as_float(b0h));
            uint32_t b1l = f2tf(b1f - __uint_as_float(b1h));
#pragma unroll
            for (int mt = 0; mt < 2; mt++) {
                mma_tf32(C[mt][n], Al[mt], b0h, b1h);
                mma_tf32(C[mt][n], Ah[mt], b0l, b1l);
                mma_tf32(C[mt][n], Ah[mt], b0h, b1h);
            }
        }
    }

    // ---- epilogue: store H (fp16) + fused attention scalars ----
#pragma unroll
    for (int mt = 0; mt < 2; mt++) {
        int rt0 = wm * 32 + mt * 16 + q;  // tile row (0..63)
        int gr0 = rbase + rt0;
        int gr1 = gr0 + 8;

#pragma unroll
        for (int n = 0; n < 8; n++) {
            int col = wn * 64 + n * 8 + 2 * rr;
            if (gr0 < NN)
                *(__half2*)&Hout[gr0 * 128 + col] = __floats2half2_rn(C[mt][n].x, C[mt][n].y);
            if (gr1 < NN)
                *(__half2*)&Hout[gr1 * 128 + col] = __floats2half2_rn(C[mt][n].z, C[mt][n].w);
        }

        if (H == 4) {
#pragma unroll
            for (int hh = 0; hh < 2; hh++) {
                float ps0 = 0.f, pd0 = 0.f, ps1 = 0.f, pd1 = 0.f;
#pragma unroll
                for (int j = 0; j < 4; j++) {
                    int n = hh * 4 + j;
                    int col = wn * 64 + n * 8 + 2 * rr;
                    float2 sv = *(const float2*)&asrc[col];
                    float2 dv = *(const float2*)&adst[col];
                    ps0 += C[mt][n].x * sv.x + C[mt][n].y * sv.y;
                    ps1 += C[mt][n].z * sv.x + C[mt][n].w * sv.y;
                    pd0 += C[mt][n].x * dv.x + C[mt][n].y * dv.y;
                    pd1 += C[mt][n].z * dv.x + C[mt][n].w * dv.y;
                }
#pragma unroll
                for (int o = 1; o <= 2; o <<= 1) {
                    ps0 += __shfl_xor_sync(0xffffffffu, ps0, o);
                    ps1 += __shfl_xor_sync(0xffffffffu, ps1, o);
                    pd0 += __shfl_xor_sync(0xffffffffu, pd0, o);
                    pd1 += __shfl_xor_sync(0xffffffffu, pd1, o);
                }
                if (rr == 0) {
                    int head = wn * 2 + hh;
                    if (gr0 < NN) { As[gr0 * 4 + head] = ps0; Ad[gr0 * 4 + head] = pd0; }
                    if (gr1 < NN) { As[gr1 * 4 + head] = ps1; Ad[gr1 * 4 + head] = pd1; }
                }
            }
        } else {
            float ps0 = 0.f, pd0 = 0.f, ps1 = 0.f, pd1 = 0.f;
#pragma unroll
            for (int n = 0; n < 8; n++) {
                int col = wn * 64 + n * 8 + 2 * rr;
                float2 sv = *(const float2*)&asrc[col];
                float2 dv = *(const float2*)&adst[col];
                ps0 += C[mt][n].x * sv.x + C[mt][n].y * sv.y;
                ps1 += C[mt][n].z * sv.x + C[mt][n].w * sv.y;
                pd0 += C[mt][n].x * dv.x + C[mt][n].y * dv.y;
                pd1 += C[mt][n].z * dv.x + C[mt][n].w * dv.y;
            }
#pragma unroll
            for (int o = 1; o <= 2; o <<= 1) {
                ps0 += __shfl_xor_sync(0xffffffffu, ps0, o);
                ps1 += __shfl_xor_sync(0xffffffffu, ps1, o);
                pd0 += __shfl_xor_sync(0xffffffffu, pd0, o);
                pd1 += __shfl_xor_sync(0xffffffffu, pd1, o);
            }
            if (rr == 0) {
                s_red[wn * 128 + rt0] = ps0;
                s_red[wn * 128 + 64 + rt0] = pd0;
                s_red[wn * 128 + rt0 + 8] = ps1;
                s_red[wn * 128 + 64 + rt0 + 8] = pd1;
            }
        }
    }

    if (H == 1) {
        __syncthreads();
        if (t < 64) {
            int r = rbase + t;
            if (r < NN) {
                As[r] = s_red[t] + s_red[128 + t];
                Ad[r] = s_red[64 + t] + s_red[192 + t];
            }
        }
    }
}

// ---------------- warp-per-node aggregation (fp16 feature gather) ----------------
#define AGG_CACHE 64
template <int H, bool ELU>
__global__ void __launch_bounds__(256) k_agg(
        const __half* __restrict__ Hf, const float* __restrict__ As,
        const float* __restrict__ Ad, const float* __restrict__ bias,
        float* __restrict__ out) {
    __shared__ int   s_idx[8][AGG_CACHE];
    __shared__ float s_lg[8][AGG_CACHE * 4];
    int wip = threadIdx.x >> 5;  // warp in block
    int warp = (blockIdx.x * blockDim.x + threadIdx.x) >> 5;
    int lane = threadIdx.x & 31;
    if (warp >= NN) return;
    int e0 = g_off[warp], e1 = g_off[warp + 1];
    int deg = e1 - e0;
    int head = (H == 4) ? (lane >> 3) : 0;

    float4 adv4;
    if (H == 4) adv4 = ((const float4*)Ad)[warp];
    else        adv4 = make_float4(Ad[warp], 0.f, 0.f, 0.f);

    // ---- pass 1: lane-parallel logits + per-head max ----
    float m0 = -1e30f, m1 = -1e30f, m2 = -1e30f, m3 = -1e30f;
    for (int j = lane; j < deg; j += 32) {
        int s = g_csr[e0 + j];
        if (H == 4) {
            float4 a4 = ((const float4*)As)[s];
            float l0 = a4.x + adv4.x; l0 = (l0 > 0.f) ? l0 : SLOPE * l0;
            float l1 = a4.y + adv4.y; l1 = (l1 > 0.f) ? l1 : SLOPE * l1;
            float l2 = a4.z + adv4.z; l2 = (l2 > 0.f) ? l2 : SLOPE * l2;
            float l3 = a4.w + adv4.w; l3 = (l3 > 0.f) ? l3 : SLOPE * l3;
            if (j < AGG_CACHE) {
                s_idx[wip][j] = s;
                *(float4*)&s_lg[wip][j * 4] = make_float4(l0, l1, l2, l3);
            }
            m0 = fmaxf(m0, l0); m1 = fmaxf(m1, l1);
            m2 = fmaxf(m2, l2); m3 = fmaxf(m3, l3);
        } else {
            float l = As[s] + adv4.x;
            l = (l > 0.f) ? l : SLOPE * l;
            if (j < AGG_CACHE) { s_idx[wip][j] = s; s_lg[wip][j * 4] = l; }
            m0 = fmaxf(m0, l);
        }
    }
#pragma unroll
    for (int o = 16; o >= 1; o >>= 1) {
        m0 = fmaxf(m0, __shfl_xor_sync(0xffffffffu, m0, o));
        if (H == 4) {
            m1 = fmaxf(m1, __shfl_xor_sync(0xffffffffu, m1, o));
            m2 = fmaxf(m2, __shfl_xor_sync(0xffffffffu, m2, o));
            m3 = fmaxf(m3, __shfl_xor_sync(0xffffffffu, m3, o));
        }
    }
    float m = m0;
    if (H == 4) m = (head == 0) ? m0 : (head == 1) ? m1 : (head == 2) ? m2 : m3;
    float adv = (H == 4) ? ((head == 0) ? adv4.x : (head == 1) ? adv4.y
                           : (head == 2) ? adv4.z : adv4.w)
                         : adv4.x;
    __syncwarp();

    // ---- pass 2: fp16 gather + exp + accumulate (8 gathers in flight) ----
    const uint2* H2 = (const uint2*)Hf;  // 4 halves per lane-slot
    float den = 0.f;
    float4 acc = make_float4(0.f, 0.f, 0.f, 0.f);
    int cached = (deg < AGG_CACHE) ? deg : AGG_CACHE;
    int e = 0;
    for (; e + 8 <= cached; e += 8) {
        int s[8];
        float w[8];
        uint2 hv[8];
#pragma unroll
        for (int j = 0; j < 8; j++) s[j] = s_idx[wip][e + j];
#pragma unroll
        for (int j = 0; j < 8; j++) hv[j] = H2[s[j] * 32 + lane];
#pragma unroll
        for (int j = 0; j < 8; j++) w[j] = __expf(s_lg[wip][(e + j) * 4 + head] - m);
#pragma unroll
        for (int j = 0; j < 8; j++) {
            float2 f0 = __half22float2(*(__half2*)&hv[j].x);
            float2 f1 = __half22float2(*(__half2*)&hv[j].y);
            den += w[j];
            acc.x = fmaf(w[j], f0.x, acc.x);
            acc.y = fmaf(w[j], f0.y, acc.y);
            acc.z = fmaf(w[j], f1.x, acc.z);
            acc.w = fmaf(w[j], f1.y, acc.w);
        }
    }
    for (; e < cached; e++) {
        int s = s_idx[wip][e];
        float w = __expf(s_lg[wip][e * 4 + head] - m);
        uint2 hv = H2[s * 32 + lane];
        float2 f0 = __half22float2(*(__half2*)&hv.x);
        float2 f1 = __half22float2(*(__half2*)&hv.y);
        den += w;
        acc.x = fmaf(w, f0.x, acc.x);
        acc.y = fmaf(w, f0.y, acc.y);
        acc.z = fmaf(w, f1.x, acc.z);
        acc.w = fmaf(w, f1.y, acc.w);
    }
    // overflow path (deg > AGG_CACHE; rare)
    for (int eo = cached; eo < deg; eo++) {
        int s = g_csr[e0 + eo];
        float a = As[s * H + head] + adv;
        a = (a > 0.f) ? a : SLOPE * a;
        float w = __expf(a - m);
        uint2 hv = H2[s * 32 + lane];
        float2 f0 = __half22float2(*(__half2*)&hv.x);
        float2 f1 = __half22float2(*(__half2*)&hv.y);
        den += w;
        acc.x = fmaf(w, f0.x, acc.x);
        acc.y = fmaf(w, f0.y, acc.y);
        acc.z = fmaf(w, f1.x, acc.z);
        acc.w = fmaf(w, f1.y, acc.w);
    }

    float inv = 1.f / den;
    float4 b = ((const float4*)bias)[lane];
    float4 o;
    o.x = acc.x * inv + b.x;
    o.y = acc.y * inv + b.y;
    o.z = acc.z * inv + b.z;
    o.w = acc.w * inv + b.w;
    if (ELU) {
        o.x = (o.x > 0.f) ? o.x : expm1f(o.x);
        o.y = (o.y > 0.f) ? o.y : expm1f(o.y);
        o.z = (o.z > 0.f) ? o.z : expm1f(o.z);
        o.w = (o.w > 0.f) ? o.w : expm1f(o.w);
    }
    ((float4*)out)[warp * 32 + lane] = o;
}

// ---------------- host launcher ----------------
extern "C" void kernel_launch(void* const* d_in, const int* in_sizes, int n_in,
                              void* d_out, int out_size) {
    const float* x   = (const float*)d_in[0];
    const int*   ei  = (const int*)d_in[1];
    const float* W1  = (const float*)d_in[2];
    const float* as1 = (const float*)d_in[3];
    const float* ad1 = (const float*)d_in[4];
    const float* b1  = (const float*)d_in[5];
    const float* W2  = (const float*)d_in[6];
    const float* as2 = (const float*)d_in[7];
    const float* ad2 = (const float*)d_in[8];
    const float* b2  = (const float*)d_in[9];
    const float* W3  = (const float*)d_in[10];
    const float* as3 = (const float*)d_in[11];
    const float* ad3 = (const float*)d_in[12];
    const float* b3  = (const float*)d_in[13];
    const int* src = ei;
    const int* dst = ei + EE;

    const int smem_gemm = (16384 + 8192 + 256) * 4;  // ~97 KB
    cudaFuncSetAttribute(k_gemm<4>, cudaFuncAttributeMaxDynamicSharedMemorySize, smem_gemm);
    cudaFuncSetAttribute(k_gemm<1>, cudaFuncAttributeMaxDynamicSharedMemorySize, smem_gemm);

    __half* d_h = nullptr;
    float *d_feat, *d_As, *d_Ad;
    cudaGetSymbolAddress((void**)&d_h, g_h);
    cudaGetSymbolAddress((void**)&d_feat, g_feat);
    cudaGetSymbolAddress((void**)&d_As, g_as);
    cudaGetSymbolAddress((void**)&d_Ad, g_ad);

    // side stream + events (host objects, created once; no device memory)
    static cudaStream_t s2 = nullptr;
    static cudaEvent_t ev_fork = nullptr, ev_csr = nullptr;
    if (!s2) {
        cudaStreamCreateWithFlags(&s2, cudaStreamNonBlocking);
        cudaEventCreateWithFlags(&ev_fork, cudaEventDisableTiming);
        cudaEventCreateWithFlags(&ev_csr, cudaEventDisableTiming);
    }

    const int gemm_blocks = (NN + 63) / 64;              // 1563
    const int node_warp_blocks = (NN * 32 + 255) / 256;  // warp per node
    const int edge_blocks = (EE + 255) / 256;

    // ---- fork: CSR build on side stream, overlapped with layer-1 GEMM ----
    cudaEventRecord(ev_fork, 0);
    cudaStreamWaitEvent(s2, ev_fork, 0);
    k_init<<<(NN + 255) / 256, 256, 0, s2>>>();
    k_count<<<edge_blocks, 256, 0, s2>>>(dst);
    k_scan<<<1, 1024, 0, s2>>>();
    k_scatter<<<(ET + 255) / 256, 256, 0, s2>>>(src, dst);
    cudaEventRecord(ev_csr, s2);

    // ---- layer 1 (default stream, concurrent with CSR build) ----
    k_gemm<4><<<gemm_blocks, 128, smem_gemm>>>(x, W1, as1, ad1, d_h, d_As, d_Ad);
    cudaStreamWaitEvent(0, ev_csr, 0);  // CSR ready before agg
    k_agg<4, true><<<node_warp_blocks, 256>>>(d_h, d_As, d_Ad, b1, d_feat);

    // ---- layer 2 ----
    k_gemm<4><<<gemm_blocks, 128, smem_gemm>>>(d_feat, W2, as2, ad2, d_h, d_As, d_Ad);
    k_agg<4, true><<<node_warp_blocks, 256>>>(d_h, d_As, d_Ad, b2, d_feat);

    // ---- layer 3 (heads=1, no ELU) ----
    k_gemm<1><<<gemm_blocks, 128, smem_gemm>>>(d_feat, W3, as3, ad3, d_h, d_As, d_Ad);
    k_agg<1, false><<<node_warp_blocks, 256>>>(d_h, d_As, d_Ad, b3, (float*)d_out);
}

// round 14
// speedup vs baseline: 1.2232x; 1.0245x over previous
#include <cuda_runtime.h>
#include <cuda_fp16.h>
#include <math.h>
#include <stdint.h>

#define NN 100000
#define EE 1600000
#define ET (EE + NN)
#define SLOPE 0.2f
#define SCAN_CHUNK 2048
#define NB ((NN + SCAN_CHUNK - 1) / SCAN_CHUNK)   // 49

// ---------------- scratch (static device globals; no runtime allocation) ----------------
__device__ __align__(16) __half g_h[NN * 128];    // transformed features (fp16 for gather)
__device__ __align__(16) float g_feat[NN * 128];  // layer activations (post bias+ELU)
__device__ __align__(16) float g_as[NN * 4];      // per-node attention src scalar (per head)
__device__ __align__(16) float g_ad[NN * 4];      // per-node attention dst scalar (per head)
__device__ int g_off[NN + 1];                     // CSR offsets (by dst)
__device__ int g_cur[NN];                         // scatter cursors
__device__ int g_csr[ET];                         // CSR: src index per incoming edge
__device__ int g_part[64];                        // scan block partials

// ---------------- CSR build ----------------
__global__ void k_init() {
    int i = blockIdx.x * blockDim.x + threadIdx.x;
    if (i < NN) g_off[i] = 1;  // self loop
}

__global__ void k_count(const int* __restrict__ dst) {
    int i = blockIdx.x * blockDim.x + threadIdx.x;
    int idx = i * 2;
    if (idx + 1 < EE) {
        int2 d = ((const int2*)dst)[i];
        atomicAdd(&g_off[d.x], 1);
        atomicAdd(&g_off[d.y], 1);
    } else if (idx < EE) {
        atomicAdd(&g_off[dst[idx]], 1);
    }
}

// phase A: per-block (2048-elem) local exclusive scan, block totals -> g_part
__global__ void k_scanA() {
    __shared__ int swarp[32];
    int b = blockIdx.x, t = threadIdx.x, lane = t & 31, wid = t >> 5;
    int i0 = b * SCAN_CHUNK + 2 * t, i1 = i0 + 1;
    int v0 = (i0 < NN) ? g_off[i0] : 0;
    int v1 = (i1 < NN) ? g_off[i1] : 0;
    int s = v0 + v1;
    int x = s;
#pragma unroll
    for (int o = 1; o < 32; o <<= 1) {
        int y = __shfl_up_sync(0xffffffffu, x, o);
        if (lane >= o) x += y;
    }
    if (lane == 31) swarp[wid] = x;
    __syncthreads();
    if (wid == 0) {
        int y = swarp[lane];
#pragma unroll
        for (int o = 1; o < 32; o <<= 1) {
            int z = __shfl_up_sync(0xffffffffu, y, o);
            if (lane >= o) y += z;
        }
        swarp[lane] = y;
    }
    __syncthreads();
    int excl = x - s + ((wid > 0) ? swarp[wid - 1] : 0);
    if (i0 < NN) g_off[i0] = excl;
    if (i1 < NN) g_off[i1] = excl + v0;
    if (t == 1023) g_part[b] = excl + s;  // block total
}

// phase B: single small block scans the NB partials (exclusive, in place)
__global__ void k_scanB() {
    int t = threadIdx.x;  // 64 threads
    __shared__ int w0tot;
    int v = (t < NB) ? g_part[t] : 0;
    int x = v;
#pragma unroll
    for (int o = 1; o < 32; o <<= 1) {
        int y = __shfl_up_sync(0xffffffffu, x, o);
        if ((t & 31) >= o) x += y;
    }
    if (t == 31) w0tot = x;
    __syncthreads();
    if (t >= 32) x += w0tot;
    int excl = x - v;
    if (t < NB) g_part[t] = excl;
    if (t == NB - 1) g_off[NN] = excl + v;  // = ET
}

// phase C: add block offsets; write cursors
__global__ void k_scanC() {
    int i = blockIdx.x * blockDim.x + threadIdx.x;
    if (i < NN) {
        int val = g_off[i] + g_part[i / SCAN_CHUNK];
        g_off[i] = val;
        g_cur[i] = val;
    }
}

__global__ void k_scatter(const int* __restrict__ src, const int* __restrict__ dst) {
    int i = blockIdx.x * blockDim.x + threadIdx.x;
    if (i < ET) {
        int s, d;
        if (i < EE) { s = src[i]; d = dst[i]; }
        else        { s = i - EE; d = s; }
        int pos = atomicAdd(&g_cur[d], 1);
        g_csr[pos] = s;
    }
}

// ---------------- tf32 helpers ----------------
__device__ __forceinline__ uint32_t f2tf(float f) {
    uint32_t u;
    asm("cvt.rna.tf32.f32 %0, %1;" : "=r"(u) : "f"(f));
    return u;
}

__device__ __forceinline__ void mma_tf32(float4& c, const uint32_t* a, uint32_t b0, uint32_t b1) {
    asm volatile(
        "mma.sync.aligned.m16n8k8.row.col.f32.tf32.tf32.f32 "
        "{%0,%1,%2,%3}, {%4,%5,%6,%7}, {%8,%9}, {%0,%1,%2,%3};\n"
        : "+f"(c.x), "+f"(c.y), "+f"(c.z), "+f"(c.w)
        : "r"(a[0]), "r"(a[1]), "r"(a[2]), "r"(a[3]), "r"(b0), "r"(b1));
}

// ---------------- tensor-core GEMM (3xTF32) + fused attention scalars ----------------
// Stores H in fp16 (halves the downstream gather traffic). As/Ad from fp32 accums.
template <int H>
__global__ void __launch_bounds__(128, 2) k_gemm(
        const float* __restrict__ X, const float* __restrict__ W,
        const float* __restrict__ asrc, const float* __restrict__ adst,
        __half* __restrict__ Hout, float* __restrict__ As, float* __restrict__ Ad) {
    extern __shared__ float sm[];
    float* Ws = sm;              // 16384 floats
    float* Xs = sm + 16384;      // 8192 floats
    float* s_red = sm + 24576;   // 256 floats (H==1 cross-warp reduce)
    int t = threadIdx.x;
    int lane = t & 31, wid = t >> 5;
    int wm = wid >> 1, wn = wid & 1;
    int q = lane >> 2;           // 0..7
    int rr = lane & 3;           // 0..3
    int rbase = blockIdx.x * 64;

    // ---- load W (swizzled) ----
    const float4* W4 = (const float4*)W;
    float4* Ws4 = (float4*)Ws;
#pragma unroll
    for (int i = 0; i < 32; i++) {
        int idx = t + i * 128;              // 0..4095
        int k = idx >> 5, c4 = idx & 31;
        Ws4[k * 32 + (c4 ^ ((k & 3) << 1))] = W4[idx];
    }
    // ---- load X tile (swizzled, zero-padded) ----
    const float4* X4 = (const float4*)X;
    float4* Xs4 = (float4*)Xs;
#pragma unroll
    for (int i = 0; i < 16; i++) {
        int idx = t + i * 128;
        int row = idx >> 5, c4 = idx & 31;
        int r = rbase + row;
        float4 v = make_float4(0.f, 0.f, 0.f, 0.f);
        if (r < NN) v = X4[r * 32 + c4];
        Xs4[row * 32 + (c4 ^ (row & 7))] = v;
    }
    __syncthreads();

    float4 C[2][8];
#pragma unroll
    for (int mt = 0; mt < 2; mt++)
#pragma unroll
        for (int n = 0; n < 8; n++) C[mt][n] = make_float4(0.f, 0.f, 0.f, 0.f);

    int asw = q << 2;  // A swizzle
    int bsw = rr << 3; // B swizzle

#pragma unroll 2
    for (int kc = 0; kc < 16; kc++) {
        int k0 = kc * 8 + rr;
        uint32_t Ah[2][4], Al[2][4];
#pragma unroll
        for (int mt = 0; mt < 2; mt++) {
            int r0 = wm * 32 + mt * 16 + q;
            int r1 = r0 + 8;
            float a0 = Xs[r0 * 128 + (k0 ^ asw)];
            float a1 = Xs[r1 * 128 + (k0 ^ asw)];
            float a2 = Xs[r0 * 128 + ((k0 + 4) ^ asw)];
            float a3 = Xs[r1 * 128 + ((k0 + 4) ^ asw)];
            Ah[mt][0] = f2tf(a0); Al[mt][0] = f2tf(a0 - __uint_as_float(Ah[mt][0]));
            Ah[mt][1] = f2tf(a1); Al[mt][1] = f2tf(a1 - __uint_as_float(Ah[mt][1]));
            Ah[mt][2] = f2tf(a2); Al[mt][2] = f2tf(a2 - __uint_as_float(Ah[mt][2]));
            Ah[mt][3] = f2tf(a3); Al[mt][3] = f2tf(a3 - __uint_as_float(Ah[mt][3]));
        }
#pragma unroll
        for (int n = 0; n < 8; n++) {
            int col = wn * 64 + n * 8 + q;
            float b0f = Ws[k0 * 128 + (col ^ bsw)];
            float b1f = Ws[(k0 + 4) * 128 + (col ^ bsw)];
            uint32_t b0h = f2tf(b0f), b1h = f2tf(b1f);
            uint32_t b0l = f2tf(b0f - __uint_as_float(b0h));
            uint32_t b1l = f2tf(b1f - __uint_as_float(b1h));
#pragma unroll
            for (int mt = 0; mt < 2; mt++) {
                mma_tf32(C[mt][n], Al[mt], b0h, b1h);
                mma_tf32(C[mt][n], Ah[mt], b0l, b1l);
                mma_tf32(C[mt][n], Ah[mt], b0h, b1h);
            }
        }
    }

    // ---- epilogue: store H (fp16) + fused attention scalars ----
#pragma unroll
    for (int mt = 0; mt < 2; mt++) {
        int rt0 = wm * 32 + mt * 16 + q;  // tile row (0..63)
        int gr0 = rbase + rt0;
        int gr1 = gr0 + 8;

#pragma unroll
        for (int n = 0; n < 8; n++) {
            int col = wn * 64 + n * 8 + 2 * rr;
            if (gr0 < NN)
                *(__half2*)&Hout[gr0 * 128 + col] = __floats2half2_rn(C[mt][n].x, C[mt][n].y);
            if (gr1 < NN)
                *(__half2*)&Hout[gr1 * 128 + col] = __floats2half2_rn(C[mt][n].z, C[mt][n].w);
        }

        if (H == 4) {
#pragma unroll
            for (int hh = 0; hh < 2; hh++) {
                float ps0 = 0.f, pd0 = 0.f, ps1 = 0.f, pd1 = 0.f;
#pragma unroll
                for (int j = 0; j < 4; j++) {
                    int n = hh * 4 + j;
                    int col = wn * 64 + n * 8 + 2 * rr;
                    float2 sv = *(const float2*)&asrc[col];
                    float2 dv = *(const float2*)&adst[col];
                    ps0 += C[mt][n].x * sv.x + C[mt][n].y * sv.y;
                    ps1 += C[mt][n].z * sv.x + C[mt][n].w * sv.y;
                    pd0 += C[mt][n].x * dv.x + C[mt][n].y * dv.y;
                    pd1 += C[mt][n].z * dv.x + C[mt][n].w * dv.y;
                }
#pragma unroll
                for (int o = 1; o <= 2; o <<= 1) {
                    ps0 += __shfl_xor_sync(0xffffffffu, ps0, o);
                    ps1 += __shfl_xor_sync(0xffffffffu, ps1, o);
                    pd0 += __shfl_xor_sync(0xffffffffu, pd0, o);
                    pd1 += __shfl_xor_sync(0xffffffffu, pd1, o);
                }
                if (rr == 0) {
                    int head = wn * 2 + hh;
                    if (gr0 < NN) { As[gr0 * 4 + head] = ps0; Ad[gr0 * 4 + head] = pd0; }
                    if (gr1 < NN) { As[gr1 * 4 + head] = ps1; Ad[gr1 * 4 + head] = pd1; }
                }
            }
        } else {
            float ps0 = 0.f, pd0 = 0.f, ps1 = 0.f, pd1 = 0.f;
#pragma unroll
            for (int n = 0; n < 8; n++) {
                int col = wn * 64 + n * 8 + 2 * rr;
                float2 sv = *(const float2*)&asrc[col];
                float2 dv = *(const float2*)&adst[col];
                ps0 += C[mt][n].x * sv.x + C[mt][n].y * sv.y;
                ps1 += C[mt][n].z * sv.x + C[mt][n].w * sv.y;
                pd0 += C[mt][n].x * dv.x + C[mt][n].y * dv.y;
                pd1 += C[mt][n].z * dv.x + C[mt][n].w * dv.y;
            }
#pragma unroll
            for (int o = 1; o <= 2; o <<= 1) {
                ps0 += __shfl_xor_sync(0xffffffffu, ps0, o);
                ps1 += __shfl_xor_sync(0xffffffffu, ps1, o);
                pd0 += __shfl_xor_sync(0xffffffffu, pd0, o);
                pd1 += __shfl_xor_sync(0xffffffffu, pd1, o);
            }
            if (rr == 0) {
                s_red[wn * 128 + rt0] = ps0;
                s_red[wn * 128 + 64 + rt0] = pd0;
                s_red[wn * 128 + rt0 + 8] = ps1;
                s_red[wn * 128 + 64 + rt0 + 8] = pd1;
            }
        }
    }

    if (H == 1) {
        __syncthreads();
        if (t < 64) {
            int r = rbase + t;
            if (r < NN) {
                As[r] = s_red[t] + s_red[128 + t];
                Ad[r] = s_red[64 + t] + s_red[192 + t];
            }
        }
    }
}

// ---------------- warp-per-node aggregation (fp16 gather, predicated batches) ----------------
#define AGG_CACHE 64
template <int H, bool ELU>
__global__ void __launch_bounds__(256) k_agg(
        const __half* __restrict__ Hf, const float* __restrict__ As,
        const float* __restrict__ Ad, const float* __restrict__ bias,
        float* __restrict__ out) {
    __shared__ int   s_idx[8][AGG_CACHE];
    __shared__ float s_lg[8][AGG_CACHE * 4];
    int wip = threadIdx.x >> 5;  // warp in block
    int warp = (blockIdx.x * blockDim.x + threadIdx.x) >> 5;
    int lane = threadIdx.x & 31;
    if (warp >= NN) return;
    int e0 = g_off[warp], e1 = g_off[warp + 1];
    int deg = e1 - e0;
    int head = (H == 4) ? (lane >> 3) : 0;

    float4 adv4;
    if (H == 4) adv4 = ((const float4*)Ad)[warp];
    else        adv4 = make_float4(Ad[warp], 0.f, 0.f, 0.f);

    // ---- pass 1: lane-parallel logits + per-head max ----
    float m0 = -1e30f, m1 = -1e30f, m2 = -1e30f, m3 = -1e30f;
    for (int j = lane; j < deg; j += 32) {
        int s = g_csr[e0 + j];
        if (H == 4) {
            float4 a4 = ((const float4*)As)[s];
            float l0 = a4.x + adv4.x; l0 = (l0 > 0.f) ? l0 : SLOPE * l0;
            float l1 = a4.y + adv4.y; l1 = (l1 > 0.f) ? l1 : SLOPE * l1;
            float l2 = a4.z + adv4.z; l2 = (l2 > 0.f) ? l2 : SLOPE * l2;
            float l3 = a4.w + adv4.w; l3 = (l3 > 0.f) ? l3 : SLOPE * l3;
            if (j < AGG_CACHE) {
                s_idx[wip][j] = s;
                *(float4*)&s_lg[wip][j * 4] = make_float4(l0, l1, l2, l3);
            }
            m0 = fmaxf(m0, l0); m1 = fmaxf(m1, l1);
            m2 = fmaxf(m2, l2); m3 = fmaxf(m3, l3);
        } else {
            float l = As[s] + adv4.x;
            l = (l > 0.f) ? l : SLOPE * l;
            if (j < AGG_CACHE) { s_idx[wip][j] = s; s_lg[wip][j * 4] = l; }
            m0 = fmaxf(m0, l);
        }
    }
#pragma unroll
    for (int o = 16; o >= 1; o >>= 1) {
        m0 = fmaxf(m0, __shfl_xor_sync(0xffffffffu, m0, o));
        if (H == 4) {
            m1 = fmaxf(m1, __shfl_xor_sync(0xffffffffu, m1, o));
            m2 = fmaxf(m2, __shfl_xor_sync(0xffffffffu, m2, o));
            m3 = fmaxf(m3, __shfl_xor_sync(0xffffffffu, m3, o));
        }
    }
    float m = m0;
    if (H == 4) m = (head == 0) ? m0 : (head == 1) ? m1 : (head == 2) ? m2 : m3;
    float adv = (H == 4) ? ((head == 0) ? adv4.x : (head == 1) ? adv4.y
                           : (head == 2) ? adv4.z : adv4.w)
                         : adv4.x;
    __syncwarp();

    // ---- pass 2: predicated 8-wide batches (no scalar tail; MLP=8 throughout) ----
    const uint2* H2 = (const uint2*)Hf;  // 4 halves per lane-slot
    float den = 0.f;
    float4 acc = make_float4(0.f, 0.f, 0.f, 0.f);
    int cached = (deg < AGG_CACHE) ? deg : AGG_CACHE;
    for (int e = 0; e < cached; e += 8) {
        int idx[8];
        int s[8];
        float w[8];
        uint2 hv[8];
#pragma unroll
        for (int j = 0; j < 8; j++) {
            int k = e + j;
            idx[j] = (k < cached) ? k : (cached - 1);
        }
#pragma unroll
        for (int j = 0; j < 8; j++) s[j] = s_idx[wip][idx[j]];
#pragma unroll
        for (int j = 0; j < 8; j++) hv[j] = H2[s[j] * 32 + lane];
#pragma unroll
        for (int j = 0; j < 8; j++) {
            float we = __expf(s_lg[wip][idx[j] * 4 + head] - m);
            w[j] = (e + j < cached) ? we : 0.f;
        }
#pragma unroll
        for (int j = 0; j < 8; j++) {
            float2 f0 = __half22float2(*(__half2*)&hv[j].x);
            float2 f1 = __half22float2(*(__half2*)&hv[j].y);
            den += w[j];
            acc.x = fmaf(w[j], f0.x, acc.x);
            acc.y = fmaf(w[j], f0.y, acc.y);
            acc.z = fmaf(w[j], f1.x, acc.z);
            acc.w = fmaf(w[j], f1.y, acc.w);
        }
    }
    // overflow path (deg > AGG_CACHE; rare)
    for (int eo = cached; eo < deg; eo++) {
        int s = g_csr[e0 + eo];
        float a = As[s * H + head] + adv;
        a = (a > 0.f) ? a : SLOPE * a;
        float w = __expf(a - m);
        uint2 hv = H2[s * 32 + lane];
        float2 f0 = __half22float2(*(__half2*)&hv.x);
        float2 f1 = __half22float2(*(__half2*)&hv.y);
        den += w;
        acc.x = fmaf(w, f0.x, acc.x);
        acc.y = fmaf(w, f0.y, acc.y);
        acc.z = fmaf(w, f1.x, acc.z);
        acc.w = fmaf(w, f1.y, acc.w);
    }

    float inv = 1.f / den;
    float4 b = ((const float4*)bias)[lane];
    float4 o;
    o.x = acc.x * inv + b.x;
    o.y = acc.y * inv + b.y;
    o.z = acc.z * inv + b.z;
    o.w = acc.w * inv + b.w;
    if (ELU) {
        o.x = (o.x > 0.f) ? o.x : expm1f(o.x);
        o.y = (o.y > 0.f) ? o.y : expm1f(o.y);
        o.z = (o.z > 0.f) ? o.z : expm1f(o.z);
        o.w = (o.w > 0.f) ? o.w : expm1f(o.w);
    }
    ((float4*)out)[warp * 32 + lane] = o;
}

// ---------------- host launcher ----------------
extern "C" void kernel_launch(void* const* d_in, const int* in_sizes, int n_in,
                              void* d_out, int out_size) {
    const float* x   = (const float*)d_in[0];
    const int*   ei  = (const int*)d_in[1];
    const float* W1  = (const float*)d_in[2];
    const float* as1 = (const float*)d_in[3];
    const float* ad1 = (const float*)d_in[4];
    const float* b1  = (const float*)d_in[5];
    const float* W2  = (const float*)d_in[6];
    const float* as2 = (const float*)d_in[7];
    const float* ad2 = (const float*)d_in[8];
    const float* b2  = (const float*)d_in[9];
    const float* W3  = (const float*)d_in[10];
    const float* as3 = (const float*)d_in[11];
    const float* ad3 = (const float*)d_in[12];
    const float* b3  = (const float*)d_in[13];
    const int* src = ei;
    const int* dst = ei + EE;

    const int smem_gemm = (16384 + 8192 + 256) * 4;  // ~97 KB
    cudaFuncSetAttribute(k_gemm<4>, cudaFuncAttributeMaxDynamicSharedMemorySize, smem_gemm);
    cudaFuncSetAttribute(k_gemm<1>, cudaFuncAttributeMaxDynamicSharedMemorySize, smem_gemm);

    __half* d_h = nullptr;
    float *d_feat, *d_As, *d_Ad;
    cudaGetSymbolAddress((void**)&d_h, g_h);
    cudaGetSymbolAddress((void**)&d_feat, g_feat);
    cudaGetSymbolAddress((void**)&d_As, g_as);
    cudaGetSymbolAddress((void**)&d_Ad, g_ad);

    // side stream + events (host objects, created once; no device memory)
    static cudaStream_t s2 = nullptr;
    static cudaEvent_t ev_fork = nullptr, ev_csr = nullptr;
    if (!s2) {
        cudaStreamCreateWithFlags(&s2, cudaStreamNonBlocking);
        cudaEventCreateWithFlags(&ev_fork, cudaEventDisableTiming);
        cudaEventCreateWithFlags(&ev_csr, cudaEventDisableTiming);
    }

    const int gemm_blocks = (NN + 63) / 64;              // 1563
    const int node_warp_blocks = (NN * 32 + 255) / 256;  // warp per node

    // ---- fork: CSR build on side stream, overlapped with layer-1 GEMM ----
    cudaEventRecord(ev_fork, 0);
    cudaStreamWaitEvent(s2, ev_fork, 0);
    k_init<<<(NN + 255) / 256, 256, 0, s2>>>();
    k_count<<<(EE / 2 + 255) / 256, 256, 0, s2>>>(dst);
    k_scanA<<<NB, 1024, 0, s2>>>();
    k_scanB<<<1, 64, 0, s2>>>();
    k_scanC<<<(NN + 255) / 256, 256, 0, s2>>>();
    k_scatter<<<(ET + 255) / 256, 256, 0, s2>>>(src, dst);
    cudaEventRecord(ev_csr, s2);

    // ---- layer 1 (default stream, concurrent with CSR build) ----
    k_gemm<4><<<gemm_blocks, 128, smem_gemm>>>(x, W1, as1, ad1, d_h, d_As, d_Ad);
    cudaStreamWaitEvent(0, ev_csr, 0);  // CSR ready before agg
    k_agg<4, true><<<node_warp_blocks, 256>>>(d_h, d_As, d_Ad, b1, d_feat);

    // ---- layer 2 ----
    k_gemm<4><<<gemm_blocks, 128, smem_gemm>>>(d_feat, W2, as2, ad2, d_h, d_As, d_Ad);
    k_agg<4, true><<<node_warp_blocks, 256>>>(d_h, d_As, d_Ad, b2, d_feat);

    // ---- layer 3 (heads=1, no ELU) ----
    k_gemm<1><<<gemm_blocks, 128, smem_gemm>>>(d_feat, W3, as3, ad3, d_h, d_As, d_Ad);
    k_agg<1, false><<<node_warp_blocks, 256>>>(d_h, d_As, d_Ad, b3, (float*)d_out);
}